// round 3
// baseline (speedup 1.0000x reference)
#include <cuda_runtime.h>

// DenseGATBlock: 2-layer GAT, N=8192, D=128, heads=1, sparse adj (~1% + self loops).
// Strategy: build padded-CSR from adj once (DRAM-bound), then per layer:
//   fp32 SIMT GEMM h = x@W, per-row attention scores, sparse softmax-aggregate.

#define NN 8192
#define DD 128
#define MAXDEG 256

// Scratch (device globals; no allocation allowed)
__device__ int   g_col[NN * MAXDEG];   // 8 MB padded neighbor lists
__device__ int   g_deg[NN];
__device__ float g_h[NN * DD];         // 4 MB, L2-resident
__device__ float g_asrc[NN];
__device__ float g_adst[NN];

// ---------------------------------------------------------------------------
// Kernel 1: build padded CSR from dense adj. One block per row, 256 threads.
// Reads 268 MB once; both layers reuse the structure.
// ---------------------------------------------------------------------------
__global__ void build_csr_k(const float* __restrict__ adj) {
    int i = blockIdx.x;
    __shared__ int cnt;
    if (threadIdx.x == 0) cnt = 0;
    __syncthreads();
    const float4* row = (const float4*)(adj + (size_t)i * NN);
    int* outc = g_col + i * MAXDEG;
    for (int v = threadIdx.x; v < NN / 4; v += blockDim.x) {
        float4 f = row[v];
        int base = v * 4;
        if (f.x != 0.f) { int p = atomicAdd(&cnt, 1); if (p < MAXDEG) outc[p] = base; }
        if (f.y != 0.f) { int p = atomicAdd(&cnt, 1); if (p < MAXDEG) outc[p] = base + 1; }
        if (f.z != 0.f) { int p = atomicAdd(&cnt, 1); if (p < MAXDEG) outc[p] = base + 2; }
        if (f.w != 0.f) { int p = atomicAdd(&cnt, 1); if (p < MAXDEG) outc[p] = base + 3; }
    }
    __syncthreads();
    if (threadIdx.x == 0) g_deg[i] = cnt < MAXDEG ? cnt : MAXDEG;
}

// ---------------------------------------------------------------------------
// Kernel 2: fp32 GEMM  h[N,128] = A[N,128] @ W[128,128]
// BM=64, BN=128, BK=32, 256 threads, 8x4 register tile per thread.
// ---------------------------------------------------------------------------
#define BM 64
#define BK 32
__global__ void gemm128_k(const float* __restrict__ A, const float* __restrict__ W,
                          float* __restrict__ C) {
    __shared__ float As[BM][BK];     // 8 KB
    __shared__ float Bs[BK][DD];     // 16 KB
    int tid = threadIdx.x;
    int rowBase = blockIdx.x * BM;
    int trow = tid >> 5;             // 0..7  (same across a warp)
    int tcol = tid & 31;             // 0..31
    float acc[8][4];
#pragma unroll
    for (int a = 0; a < 8; a++)
#pragma unroll
        for (int b = 0; b < 4; b++) acc[a][b] = 0.f;

    for (int k0 = 0; k0 < DD; k0 += BK) {
        // load As: 64x32 floats = 512 float4, 2 per thread
#pragma unroll
        for (int v = 0; v < 2; v++) {
            int f = tid * 2 + v;
            int r = f >> 3;
            int cc = (f & 7) * 4;
            *(float4*)&As[r][cc] =
                *(const float4*)&A[(size_t)(rowBase + r) * DD + k0 + cc];
        }
        // load Bs: 32x128 floats = 1024 float4, 4 per thread
#pragma unroll
        for (int v = 0; v < 4; v++) {
            int f = tid * 4 + v;
            int r = f >> 5;
            int cc = (f & 31) * 4;
            *(float4*)&Bs[r][cc] = *(const float4*)&W[(k0 + r) * DD + cc];
        }
        __syncthreads();
#pragma unroll
        for (int kk = 0; kk < BK; kk++) {
            float a[8];
#pragma unroll
            for (int ii = 0; ii < 8; ii++) a[ii] = As[trow * 8 + ii][kk];  // warp-broadcast
            float4 bv = *(float4*)&Bs[kk][tcol * 4];                       // conflict-free
#pragma unroll
            for (int ii = 0; ii < 8; ii++) {
                acc[ii][0] += a[ii] * bv.x;
                acc[ii][1] += a[ii] * bv.y;
                acc[ii][2] += a[ii] * bv.z;
                acc[ii][3] += a[ii] * bv.w;
            }
        }
        __syncthreads();
    }
#pragma unroll
    for (int ii = 0; ii < 8; ii++) {
        float4 o = make_float4(acc[ii][0], acc[ii][1], acc[ii][2], acc[ii][3]);
        *(float4*)&C[(size_t)(rowBase + trow * 8 + ii) * DD + tcol * 4] = o;
    }
}

// ---------------------------------------------------------------------------
// Kernel 3: attention scores a_src[i] = h[i].att_src, a_dst[i] = h[i].att_dst
// One warp per row; 8 warps per block.
// ---------------------------------------------------------------------------
__global__ void attscores_k(const float* __restrict__ h,
                            const float* __restrict__ att_src,
                            const float* __restrict__ att_dst) {
    int warp = threadIdx.x >> 5;
    int lane = threadIdx.x & 31;
    int row = blockIdx.x * 8 + warp;
    const float* hr = h + (size_t)row * DD;
    float s = 0.f, d = 0.f;
#pragma unroll
    for (int k = lane; k < DD; k += 32) {
        float hv = hr[k];
        s += hv * att_src[k];
        d += hv * att_dst[k];
    }
#pragma unroll
    for (int o = 16; o > 0; o >>= 1) {
        s += __shfl_xor_sync(0xffffffffu, s, o);
        d += __shfl_xor_sync(0xffffffffu, d, o);
    }
    if (lane == 0) { g_asrc[row] = s; g_adst[row] = d; }
}

// ---------------------------------------------------------------------------
// Kernel 4: per-row masked softmax + neighbor aggregation.
// One block (128 threads) per row; thread c owns output channel c.
// ---------------------------------------------------------------------------
__global__ void aggregate_k(const float* __restrict__ h,
                            const float* __restrict__ bias,
                            float* __restrict__ out, int doRelu) {
    int i = blockIdx.x;
    int tid = threadIdx.x;
    __shared__ int   s_col[MAXDEG];
    __shared__ float s_w[MAXDEG];
    __shared__ float s_red[128];

    int deg = g_deg[i];
    float adsti = g_adst[i];

    // edge scores e = leaky_relu(a_src[j] + a_dst[i])
    for (int j = tid; j < deg; j += 128) {
        int c = g_col[i * MAXDEG + j];
        s_col[j] = c;
        float e = g_asrc[c] + adsti;
        e = (e >= 0.f) ? e : 0.2f * e;
        s_w[j] = e;
    }
    __syncthreads();

    // block-reduce max
    float m = -1e30f;
    for (int j = tid; j < deg; j += 128) m = fmaxf(m, s_w[j]);
    s_red[tid] = m;
    __syncthreads();
#pragma unroll
    for (int s = 64; s > 0; s >>= 1) {
        if (tid < s) s_red[tid] = fmaxf(s_red[tid], s_red[tid + s]);
        __syncthreads();
    }
    m = s_red[0];
    __syncthreads();

    // exp + block-reduce sum
    float sum = 0.f;
    for (int j = tid; j < deg; j += 128) {
        float w = __expf(s_w[j] - m);
        s_w[j] = w;
        sum += w;
    }
    s_red[tid] = sum;
    __syncthreads();
#pragma unroll
    for (int s = 64; s > 0; s >>= 1) {
        if (tid < s) s_red[tid] += s_red[tid + s];
        __syncthreads();
    }
    float inv = 1.0f / s_red[0];

    // weighted gather-aggregate: 4 independent accumulators for ILP/MLP
    float a0 = 0.f, a1 = 0.f, a2 = 0.f, a3 = 0.f;
    int j = 0;
    for (; j + 4 <= deg; j += 4) {
        a0 += s_w[j + 0] * h[(size_t)s_col[j + 0] * DD + tid];
        a1 += s_w[j + 1] * h[(size_t)s_col[j + 1] * DD + tid];
        a2 += s_w[j + 2] * h[(size_t)s_col[j + 2] * DD + tid];
        a3 += s_w[j + 3] * h[(size_t)s_col[j + 3] * DD + tid];
    }
    for (; j < deg; j++) a0 += s_w[j] * h[(size_t)s_col[j] * DD + tid];
    float o = (a0 + a1 + a2 + a3) * inv + bias[tid];
    if (doRelu) o = fmaxf(o, 0.f);
    out[(size_t)i * DD + tid] = o;
}

// ---------------------------------------------------------------------------
extern "C" void kernel_launch(void* const* d_in, const int* in_sizes, int n_in,
                              void* d_out, int out_size) {
    const float* x        = (const float*)d_in[0];
    const float* adj      = (const float*)d_in[1];
    const float* W0       = (const float*)d_in[2];
    const float* att_src0 = (const float*)d_in[3];
    const float* att_dst0 = (const float*)d_in[4];
    const float* b0       = (const float*)d_in[5];
    const float* W1       = (const float*)d_in[6];
    const float* att_src1 = (const float*)d_in[7];
    const float* att_dst1 = (const float*)d_in[8];
    const float* b1       = (const float*)d_in[9];

    float* out0 = (float*)d_out;                 // [N,128]
    float* out1 = (float*)d_out + (size_t)NN * DD;

    float* h;
    cudaGetSymbolAddress((void**)&h, g_h);

    // CSR structure (shared by both layers)
    build_csr_k<<<NN, 256>>>(adj);

    // Layer 0
    gemm128_k<<<NN / BM, 256>>>(x, W0, h);
    attscores_k<<<NN / 8, 256>>>(h, att_src0, att_dst0);
    aggregate_k<<<NN, 128>>>(h, b0, out0, /*relu=*/1);

    // Layer 1 (input = out0)
    gemm128_k<<<NN / BM, 256>>>(out0, W1, h);
    attscores_k<<<NN / 8, 256>>>(h, att_src1, att_dst1);
    aggregate_k<<<NN, 128>>>(h, b1, out1, /*relu=*/0);
}